// round 14
// baseline (speedup 1.0000x reference)
#include <cuda_runtime.h>
#include <cuda_fp16.h>
#include <cstdint>

#define N 8192
#define C 512
#define THETA 6e-5f
#define WCAP (1 << 22)      // global worklist capacity
#define LCAP 2048           // per-CTA smem worklist capacity (entries)

// ---------------- scratch (device globals; no allocation allowed) ----------------
// Problem z=0: A=Vn, B=PTn (s1).  z=1: A=Tn, B=PVn (s2).
__device__ __half g_Ah[2][N * C];     // fp16 normalized A (pass-1 GEMM)
__device__ __half g_Bh[2][N * C];     // fp16 normalized B
__device__ float  g_Af[2][N * C];     // fp32 normalized A (pass-2 exact dots)
__device__ float  g_Bf[2][N * C];     // fp32 normalized B
__device__ float  g_diag[2][N];       // exact fp32 diagonals
__device__ int    g_cnt[2][N];
__device__ int    g_nwork;
__device__ uint32_t g_work[WCAP];     // packed (z<<26)|(i<<13)|j
__device__ float g_colsum[4][64][C];
__device__ float g_colsq[4][64][C];

__device__ __forceinline__ uint32_t smem_u32(const void* p) {
    uint32_t a;
    asm("{ .reg .u64 t; cvta.to.shared.u64 t, %1; cvt.u32.u64 %0, t; }" : "=r"(a) : "l"(p));
    return a;
}

// ---------------- kernel 0: zero count accumulators (graph replays!) ------------
__global__ void zero_cnt_kernel() {
    int i = blockIdx.x * blockDim.x + threadIdx.x;
    if (i < N) { g_cnt[0][i] = 0; g_cnt[1][i] = 0; }
    if (i == 0) g_nwork = 0;
}

__device__ __forceinline__ float dot4(float4 a, float4 b) {
    return a.x * b.x + a.y * b.y + a.z * b.z + a.w * b.w;
}

__device__ __forceinline__ void store_nf(__half* h, float* f, size_t base, float4 y, float r) {
    float4 o = make_float4(y.x * r, y.y * r, y.z * r, y.w * r);
    *(float4*)(f + base) = o;
    *(__half2*)(h + base)     = __floats2half2_rn(o.x, o.y);
    *(__half2*)(h + base + 2) = __floats2half2_rn(o.z, o.w);
}

// ---------------- kernel 1: normalize -> fp16 + fp32 copies + exact diagonals ---
__global__ void normalize_kernel(const float* __restrict__ V, const float* __restrict__ T,
                                 const float* __restrict__ PV, const float* __restrict__ PT) {
    int row = blockIdx.x;
    int t   = threadIdx.x;
    size_t base = (size_t)row * C + 4 * t;

    float4 v  = *(const float4*)(V  + base);
    float4 tf = *(const float4*)(T  + base);
    float4 pv = *(const float4*)(PV + base);
    float4 pt = *(const float4*)(PT + base);

    float p0 = dot4(v, v),  p1 = dot4(tf, tf), p2 = dot4(pv, pv);
    float p3 = dot4(pt, pt), p4 = dot4(v, pt), p5 = dot4(tf, pv);

#pragma unroll
    for (int m = 16; m; m >>= 1) {
        p0 += __shfl_xor_sync(0xffffffffu, p0, m);
        p1 += __shfl_xor_sync(0xffffffffu, p1, m);
        p2 += __shfl_xor_sync(0xffffffffu, p2, m);
        p3 += __shfl_xor_sync(0xffffffffu, p3, m);
        p4 += __shfl_xor_sync(0xffffffffu, p4, m);
        p5 += __shfl_xor_sync(0xffffffffu, p5, m);
    }
    __shared__ float sm[4][6];
    int w = t >> 5;
    if ((t & 31) == 0) {
        sm[w][0] = p0; sm[w][1] = p1; sm[w][2] = p2;
        sm[w][3] = p3; sm[w][4] = p4; sm[w][5] = p5;
    }
    __syncthreads();
    float s0 = sm[0][0] + sm[1][0] + sm[2][0] + sm[3][0];
    float s1 = sm[0][1] + sm[1][1] + sm[2][1] + sm[3][1];
    float s2 = sm[0][2] + sm[1][2] + sm[2][2] + sm[3][2];
    float s3 = sm[0][3] + sm[1][3] + sm[2][3] + sm[3][3];
    float s4 = sm[0][4] + sm[1][4] + sm[2][4] + sm[3][4];
    float s5 = sm[0][5] + sm[1][5] + sm[2][5] + sm[3][5];

    float rv  = rsqrtf(s0);
    float rt_ = rsqrtf(s1);
    float rpv = rsqrtf(s2);
    float rpt = rsqrtf(s3);

    store_nf(g_Ah[0], g_Af[0], base, v,  rv);   // Vn  (A of problem 0)
    store_nf(g_Ah[1], g_Af[1], base, tf, rt_);  // Tn  (A of problem 1)
    store_nf(g_Bh[1], g_Bf[1], base, pv, rpv);  // PVn (B of problem 1)
    store_nf(g_Bh[0], g_Bf[0], base, pt, rpt);  // PTn (B of problem 0)

    if (t == 0) {
        g_diag[0][row] = s4 * rv  * rpt;  // v_n . p_t_n
        g_diag[1][row] = s5 * rt_ * rpv;  // t_n . p_v_n
    }
}

// ---------------- kernel 2: per-column partial sums for std (fp32 copies) -------
__global__ void colstats_kernel() {
    int mat = blockIdx.y, chunk = blockIdx.x, col = threadIdx.x;
    const float* M;
    switch (mat) {
        case 0: M = g_Af[0]; break;  // v_feat
        case 1: M = g_Af[1]; break;  // t_feat
        case 2: M = g_Bf[1]; break;  // p_v
        default: M = g_Bf[0]; break; // p_t
    }
    float s = 0.f, q = 0.f;
    int r0 = chunk * 128;
#pragma unroll 4
    for (int r = r0; r < r0 + 128; r++) {
        float x = M[(size_t)r * C + col];
        s += x;
        q += x * x;
    }
    g_colsum[mat][chunk][col] = s;
    g_colsq[mat][chunk][col]  = q;
}

// ---------------- kernel 3: fp16 warp-MMA GEMM, epilogue interleaved into MMA ---
// Each CTA: one 128-row tile x FOUR 128-col tiles as one continuous 32-chunk
// pipeline. Tile jt's epilogue is deferred into the FIRST chunk of tile jt+1:
// per am-slice, [epilogue ALU burst] immediately precedes the zero-C MMA that
// overwrites those acc registers, so epilogue ALU interleaves with tensor issue
// instead of stalling all warps in lockstep. Zero-C MMA also removes acc zeroing.
#define TM 128
#define TN 128
#define TK 64
#define JT 4                              // column tiles per CTA
#define STAGES 3
#define NTHR 256
#define STAGE_A (TM * 128)
#define STAGE_B (TN * 128)
#define STAGE_BYTES (STAGE_A + STAGE_B)   // 32768
#define WLIST_OFF (STAGES * STAGE_BYTES)  // 98304
#define SMEM_SIZE (WLIST_OFF + LCAP * 4)  // 106496
#define NCHT (JT * 8)                     // 32 chunks total

__device__ __forceinline__ void ldsm4(uint32_t* r, uint32_t addr) {
    asm volatile("ldmatrix.sync.aligned.m8n8.x4.shared.b16 {%0,%1,%2,%3}, [%4];"
                 : "=r"(r[0]), "=r"(r[1]), "=r"(r[2]), "=r"(r[3]) : "r"(addr));
}
__device__ __forceinline__ void mma16816(float* d, const uint32_t* a, uint32_t b0, uint32_t b1) {
    asm volatile(
        "mma.sync.aligned.m16n8k16.row.col.f32.f16.f16.f32 "
        "{%0,%1,%2,%3}, {%4,%5,%6,%7}, {%8,%9}, {%0,%1,%2,%3};"
        : "+f"(d[0]), "+f"(d[1]), "+f"(d[2]), "+f"(d[3])
        : "r"(a[0]), "r"(a[1]), "r"(a[2]), "r"(a[3]), "r"(b0), "r"(b1));
}
// D = A*B + 0  (C is a zero constant; old D contents are dead)
__device__ __forceinline__ void mma16816_z(float* d, const uint32_t* a, uint32_t b0, uint32_t b1) {
    asm volatile(
        "mma.sync.aligned.m16n8k16.row.col.f32.f16.f16.f32 "
        "{%0,%1,%2,%3}, {%4,%5,%6,%7}, {%8,%9}, {%10,%10,%10,%10};"
        : "=f"(d[0]), "=f"(d[1]), "=f"(d[2]), "=f"(d[3])
        : "r"(a[0]), "r"(a[1]), "r"(a[2]), "r"(a[3]), "r"(b0), "r"(b1), "f"(0.f));
}

__device__ __forceinline__ void load_tile(uint32_t smem_dst, const __half* __restrict__ src,
                                          int row0, int kk, int tid) {
#pragma unroll
    for (int i = 0; i < 4; i++) {
        int idx = tid + i * NTHR;
        int r  = idx >> 3;
        int cb = (idx & 7) << 4;
        uint32_t dst = smem_dst + r * 128 + (cb ^ ((r & 7) << 4));
        const void* s = (const char*)(src + (size_t)(row0 + r) * C + kk) + cb;
        asm volatile("cp.async.cg.shared.global [%0], [%1], 16;" :: "r"(dst), "l"(s));
    }
}

__global__ void __launch_bounds__(NTHR, 2) gemm_mma_kernel() {
    extern __shared__ char smem[];
    uint32_t sb = smem_u32(smem);
    int tid = threadIdx.x, lane = tid & 31, wid = tid >> 5;
    int z = blockIdx.z;
    int row0 = blockIdx.y * TM;
    int col_base = blockIdx.x * (TN * JT);

    const __half* Ah = g_Ah[z];
    const __half* Bh = g_Bh[z];

    __shared__ int s_n, s_base;
    uint32_t* s_list = (uint32_t*)(smem + WLIST_OFF);
    if (tid == 0) s_n = 0;

    auto load_chunk = [&](int t, int stage) {
        int kk = (t & 7) * TK;
        int jc = col_base + (t >> 3) * TN;
        uint32_t s = sb + stage * STAGE_BYTES;
        load_tile(s, Ah, row0, kk, tid);
        load_tile(s + STAGE_A, Bh, jc, kk, tid);
    };

    int wm = (wid >> 2) * 64;   // warp M offset
    int wn = (wid & 3) * 32;    // warp N offset

    float acc[4][4][4];         // written first by zero-C MMA; no init needed

    int cnt_lo[4] = {0, 0, 0, 0};
    int cnt_hi[4] = {0, 0, 0, 0};

    // diag values for this warp's 8 rows: loop-invariant, preload once
    float dlo_r[4], dhi_r[4];
#pragma unroll
    for (int am = 0; am < 4; am++) {
        int rlo = row0 + wm + am * 16 + (lane >> 2);
        dlo_r[am] = __ldg(&g_diag[z][rlo]);
        dhi_r[am] = __ldg(&g_diag[z][rlo + 8]);
    }

    load_chunk(0, 0);
    asm volatile("cp.async.commit_group;");
    load_chunk(1, 1);
    asm volatile("cp.async.commit_group;");

    int arow = wm + (lane & 15);
    int acb  = (lane >> 4) << 4;
    int bg   = lane >> 3;
    int bn   = wn + (bg >> 1) * 8 + (lane & 7);
    int bcb  = (bg & 1) << 4;

    int* cnt = g_cnt[z];
    uint32_t ztag = ((uint32_t)z) << 26;

    uint32_t bm0 = 0, bm1 = 0;   // band mask of the tile being retired

    // epilogue for one am-slice (16 elements) of the PREVIOUS tile
    auto epi_am = [&](int am) {
        float dl = dlo_r[am], dh = dhi_r[am];
        float dlp = dl + THETA, dlm = dl - THETA;
        float dhp = dh + THETA, dhm = dh - THETA;
        int clo = 0, chi = 0;
#pragma unroll
        for (int j = 0; j < 4; j++) {
            float v0 = acc[am][j][0], v1 = acc[am][j][1];
            float v2 = acc[am][j][2], v3 = acc[am][j][3];
            bool g0 = v0 > dlp, g1 = v1 > dlp;
            bool g2 = v2 > dhp, g3 = v3 > dhp;
            clo += (int)g0 + (int)g1;
            chi += (int)g2 + (int)g3;
            uint32_t b = (uint32_t)((v0 > dlm) != g0)
                       | ((uint32_t)((v1 > dlm) != g1) << 1)
                       | ((uint32_t)((v2 > dhm) != g2) << 2)
                       | ((uint32_t)((v3 > dhm) != g3) << 3);
            int sh = am * 16 + j * 4;
            if (am < 2) bm0 |= b << sh;
            else        bm1 |= b << (sh - 32);
        }
        cnt_lo[am] += clo;
        cnt_hi[am] += chi;
    };

    // rare slow path: decode band bits of a retired tile -> worklist
    auto decode = [&](int col0) {
        if (bm0 | bm1) {
#pragma unroll
            for (int half = 0; half < 2; half++) {
                uint32_t m = half ? bm1 : bm0;
                while (m) {
                    int b = __ffs(m) - 1;
                    m &= m - 1;
                    int bit = half * 32 + b;
                    int am = bit >> 4, j = (bit >> 2) & 3, q = bit & 3;
                    int row = row0 + wm + am * 16 + (lane >> 2) + ((q >> 1) << 3);
                    int col = col0 + wn + j * 8 + ((lane & 3) << 1) + (q & 1);
                    int k = atomicAdd(&s_n, 1);
                    if (k < LCAP) s_list[k] = ztag | ((uint32_t)row << 13) | (uint32_t)col;
                }
            }
            bm0 = 0; bm1 = 0;
        }
    };

    int cur = 0, pre = 2;
    for (int t = 0; t < NCHT; t++) {
        asm volatile("cp.async.wait_group %0;" :: "n"(1));
        __syncthreads();
        if (t + 2 < NCHT) load_chunk(t + 2, pre);
        asm volatile("cp.async.commit_group;");

        uint32_t smA = sb + cur * STAGE_BYTES;
        uint32_t smB = smA + STAGE_A;
        bool tstart = (t & 7) == 0;

#pragma unroll
        for (int ks = 0; ks < 4; ks++) {
            uint32_t af[4][4], bf[2][4];
            int kc = ks * 32;
#pragma unroll
            for (int am = 0; am < 4; am++) {
                int row = arow + am * 16;
                ldsm4(af[am], smA + row * 128 + ((kc + acb) ^ ((row & 7) << 4)));
            }
#pragma unroll
            for (int p = 0; p < 2; p++) {
                int n = bn + p * 16;
                ldsm4(bf[p], smB + n * 128 + ((kc + bcb) ^ ((n & 7) << 4)));
            }
            if (ks == 0 && tstart) {
                // retire previous tile per am-slice, interleaved with zero-C MMAs
#pragma unroll
                for (int am = 0; am < 4; am++) {
                    if (t > 0) epi_am(am);
                    mma16816_z(acc[am][0], af[am], bf[0][0], bf[0][1]);
                    mma16816_z(acc[am][1], af[am], bf[0][2], bf[0][3]);
                    mma16816_z(acc[am][2], af[am], bf[1][0], bf[1][1]);
                    mma16816_z(acc[am][3], af[am], bf[1][2], bf[1][3]);
                }
            } else {
#pragma unroll
                for (int p = 0; p < 2; p++)
#pragma unroll
                    for (int am = 0; am < 4; am++) {
                        mma16816(acc[am][2 * p],     af[am], bf[p][0], bf[p][1]);
                        mma16816(acc[am][2 * p + 1], af[am], bf[p][2], bf[p][3]);
                    }
            }
        }
        if (tstart && t > 0) decode(col_base + ((t >> 3) - 1) * TN);

        if (++cur == STAGES) cur = 0;
        if (++pre == STAGES) pre = 0;
    }

    // retire the last tile
#pragma unroll
    for (int am = 0; am < 4; am++) epi_am(am);
    decode(col_base + (JT - 1) * TN);

    // -------- final count reduction: once per kernel --------
#pragma unroll
    for (int am = 0; am < 4; am++) {
        int rlo = row0 + wm + am * 16 + (lane >> 2);
        int clo = cnt_lo[am], chi = cnt_hi[am];
        clo += __shfl_xor_sync(0xffffffffu, clo, 1);
        clo += __shfl_xor_sync(0xffffffffu, clo, 2);
        chi += __shfl_xor_sync(0xffffffffu, chi, 1);
        chi += __shfl_xor_sync(0xffffffffu, chi, 2);
        if ((lane & 3) == 0) {
            atomicAdd(&cnt[rlo], clo);
            atomicAdd(&cnt[rlo + 8], chi);
        }
    }

    // flush the per-CTA worklist with ONE global atomic
    __syncthreads();
    if (tid == 0) {
        int n = s_n < LCAP ? s_n : LCAP;
        s_base = atomicAdd(&g_nwork, n);
    }
    __syncthreads();
    int n = s_n < LCAP ? s_n : LCAP;
    for (int k = tid; k < n; k += NTHR) {
        int idx = s_base + k;
        if (idx < WCAP) g_work[idx] = s_list[k];
    }
}

// ---------------- kernel 3b: exact fp32 recheck of ambiguous pairs --------------
__global__ void recheck_kernel() {
    int nw = g_nwork;
    if (nw > WCAP) nw = WCAP;
    int gw     = (int)((blockIdx.x * blockDim.x + threadIdx.x) >> 5);
    int lane   = threadIdx.x & 31;
    int stride = (int)((gridDim.x * blockDim.x) >> 5);
    for (int w = gw; w < nw; w += stride) {
        uint32_t e = g_work[w];
        int z = (e >> 26) & 1;
        int i = (e >> 13) & 8191;
        int j = e & 8191;
        if (i == j) continue;   // diagonal: never counts
        const float* a = g_Af[z] + (size_t)i * C;
        const float* b = g_Bf[z] + (size_t)j * C;
        float s = 0.f;
#pragma unroll
        for (int seg = 0; seg < 4; seg++) {
            float4 x = *(const float4*)(a + seg * 128 + lane * 4);
            float4 y = *(const float4*)(b + seg * 128 + lane * 4);
            s += x.x * y.x + x.y * y.y + x.z * y.z + x.w * y.w;
        }
#pragma unroll
        for (int m = 16; m; m >>= 1) s += __shfl_xor_sync(0xffffffffu, s, m);
        if (lane == 0 && s > g_diag[z][i]) atomicAdd(&g_cnt[z][i], 1);
    }
}

// ---------------- kernel 4: deterministic finalize ------------------------------
__global__ void finalize_kernel(float* __restrict__ out) {
    __shared__ float sm[16];
    int t = threadIdx.x;

    auto bsum = [&](float v) -> float {
#pragma unroll
        for (int m = 16; m; m >>= 1) v += __shfl_xor_sync(0xffffffffu, v, m);
        if ((t & 31) == 0) sm[t >> 5] = v;
        __syncthreads();
        float r = 0.f;
        if (t < 32) {
            r = (t < 16) ? sm[t] : 0.f;
#pragma unroll
            for (int m = 8; m; m >>= 1) r += __shfl_xor_sync(0xffffffffu, r, m);
        }
        __syncthreads();
        return r;
    };

    float s = 0.f;
    for (int i = t; i < N; i += 512) s += g_diag[0][i] + g_diag[1][i];
    float tot = bsum(s);
    if (t == 0) out[0] = -0.5f * tot / (float)N;

    for (int m = 0; m < 4; m++) {
        float S = 0.f, Q = 0.f;
#pragma unroll 8
        for (int ch = 0; ch < 64; ch++) {
            S += g_colsum[m][ch][t];
            Q += g_colsq[m][ch][t];
        }
        float var = (Q - S * S / (float)N) / (float)(N - 1);
        float sd = sqrtf(fmaxf(var, 0.f));
        float tots = bsum(sd);
        if (t == 0) out[1 + m] = tots / (float)C;
    }

    for (int z = 0; z < 2; z++) {
        const int* cnt = g_cnt[z];
        float c1 = 0.f, c5 = 0.f, c10 = 0.f, cm = 0.f;
        for (int i = t; i < N; i += 512) {
            int p = cnt[i];
            c1  += (p < 1)  ? 1.f : 0.f;
            c5  += (p < 5)  ? 1.f : 0.f;
            c10 += (p < 10) ? 1.f : 0.f;
            cm  += (float)p;
        }
        float t1 = bsum(c1);
        float t5 = bsum(c5);
        float t10 = bsum(c10);
        float tm = bsum(cm);
        if (t == 0) {
            out[5 + 4 * z + 0] = t1 / (float)N;
            out[5 + 4 * z + 1] = t5 / (float)N;
            out[5 + 4 * z + 2] = t10 / (float)N;
            out[5 + 4 * z + 3] = tm / (float)N;
        }
    }
}

// ---------------- launch ---------------------------------------------------------
extern "C" void kernel_launch(void* const* d_in, const int* in_sizes, int n_in,
                              void* d_out, int out_size) {
    const float* V  = (const float*)d_in[0];
    const float* T  = (const float*)d_in[1];
    const float* PV = (const float*)d_in[2];
    const float* PT = (const float*)d_in[3];

    cudaFuncSetAttribute(gemm_mma_kernel, cudaFuncAttributeMaxDynamicSharedMemorySize, SMEM_SIZE);

    zero_cnt_kernel<<<16, 512>>>();
    normalize_kernel<<<N, 128>>>(V, T, PV, PT);
    colstats_kernel<<<dim3(64, 4), 512>>>();
    gemm_mma_kernel<<<dim3(N / (TN * JT), N / TM, 2), NTHR, SMEM_SIZE>>>();
    recheck_kernel<<<1024, 256>>>();
    finalize_kernel<<<1, 512>>>((float*)d_out);
}

// round 16
// speedup vs baseline: 1.0358x; 1.0358x over previous
#include <cuda_runtime.h>
#include <cuda_fp16.h>
#include <cstdint>

#define N 8192
#define C 512
#define THETA 6e-5f
#define LCAP 2048           // per-CTA smem worklist capacity (entries)

// ---------------- scratch (device globals; no allocation allowed) ----------------
// Problem z=0: A=Vn, B=PTn (s1).  z=1: A=Tn, B=PVn (s2).
__device__ __half g_Ah[2][N * C];     // fp16 normalized A (pass-1 GEMM)
__device__ __half g_Bh[2][N * C];     // fp16 normalized B
__device__ float  g_rnorm[4][N];      // 1/||row|| per matrix (V,T,PV,PT)
__device__ float  g_diag[2][N];       // exact fp32 diagonals
__device__ int    g_cnt[2][N];
__device__ float g_colsum[4][64][C];
__device__ float g_colsq[4][64][C];

__device__ __forceinline__ uint32_t smem_u32(const void* p) {
    uint32_t a;
    asm("{ .reg .u64 t; cvta.to.shared.u64 t, %1; cvt.u32.u64 %0, t; }" : "=r"(a) : "l"(p));
    return a;
}

// ---------------- kernel 0: zero count accumulators (graph replays!) ------------
__global__ void zero_cnt_kernel() {
    int i = blockIdx.x * blockDim.x + threadIdx.x;
    if (i < N) { g_cnt[0][i] = 0; g_cnt[1][i] = 0; }
}

__device__ __forceinline__ float dot4(float4 a, float4 b) {
    return a.x * b.x + a.y * b.y + a.z * b.z + a.w * b.w;
}

__device__ __forceinline__ void store_h(__half* h, size_t base, float4 y, float r) {
    *(__half2*)(h + base)     = __floats2half2_rn(y.x * r, y.y * r);
    *(__half2*)(h + base + 2) = __floats2half2_rn(y.z * r, y.w * r);
}

// ---------------- kernel 1: normalize -> fp16 copies + rnorms + exact diagonals -
__global__ void normalize_kernel(const float* __restrict__ V, const float* __restrict__ T,
                                 const float* __restrict__ PV, const float* __restrict__ PT) {
    int row = blockIdx.x;
    int t   = threadIdx.x;
    size_t base = (size_t)row * C + 4 * t;

    float4 v  = *(const float4*)(V  + base);
    float4 tf = *(const float4*)(T  + base);
    float4 pv = *(const float4*)(PV + base);
    float4 pt = *(const float4*)(PT + base);

    float p0 = dot4(v, v),  p1 = dot4(tf, tf), p2 = dot4(pv, pv);
    float p3 = dot4(pt, pt), p4 = dot4(v, pt), p5 = dot4(tf, pv);

#pragma unroll
    for (int m = 16; m; m >>= 1) {
        p0 += __shfl_xor_sync(0xffffffffu, p0, m);
        p1 += __shfl_xor_sync(0xffffffffu, p1, m);
        p2 += __shfl_xor_sync(0xffffffffu, p2, m);
        p3 += __shfl_xor_sync(0xffffffffu, p3, m);
        p4 += __shfl_xor_sync(0xffffffffu, p4, m);
        p5 += __shfl_xor_sync(0xffffffffu, p5, m);
    }
    __shared__ float sm[4][6];
    int w = t >> 5;
    if ((t & 31) == 0) {
        sm[w][0] = p0; sm[w][1] = p1; sm[w][2] = p2;
        sm[w][3] = p3; sm[w][4] = p4; sm[w][5] = p5;
    }
    __syncthreads();
    float s0 = sm[0][0] + sm[1][0] + sm[2][0] + sm[3][0];
    float s1 = sm[0][1] + sm[1][1] + sm[2][1] + sm[3][1];
    float s2 = sm[0][2] + sm[1][2] + sm[2][2] + sm[3][2];
    float s3 = sm[0][3] + sm[1][3] + sm[2][3] + sm[3][3];
    float s4 = sm[0][4] + sm[1][4] + sm[2][4] + sm[3][4];
    float s5 = sm[0][5] + sm[1][5] + sm[2][5] + sm[3][5];

    float rv  = rsqrtf(s0);
    float rt_ = rsqrtf(s1);
    float rpv = rsqrtf(s2);
    float rpt = rsqrtf(s3);

    store_h(g_Ah[0], base, v,  rv);   // Vn  (A of problem 0)
    store_h(g_Ah[1], base, tf, rt_);  // Tn  (A of problem 1)
    store_h(g_Bh[1], base, pv, rpv);  // PVn (B of problem 1)
    store_h(g_Bh[0], base, pt, rpt);  // PTn (B of problem 0)

    if (t == 0) {
        g_rnorm[0][row] = rv;
        g_rnorm[1][row] = rt_;
        g_rnorm[2][row] = rpv;
        g_rnorm[3][row] = rpt;
        g_diag[0][row] = s4 * rv  * rpt;  // v_n . p_t_n
        g_diag[1][row] = s5 * rt_ * rpv;  // t_n . p_v_n
    }
}

// ---------------- kernel 2: per-column partial sums for std (raw x rnorm) -------
__global__ void colstats_kernel(const float* __restrict__ V, const float* __restrict__ T,
                                const float* __restrict__ PV, const float* __restrict__ PT) {
    int mat = blockIdx.y, chunk = blockIdx.x, col = threadIdx.x;
    const float* M;
    switch (mat) {
        case 0: M = V; break;
        case 1: M = T; break;
        case 2: M = PV; break;
        default: M = PT; break;
    }
    const float* rn = g_rnorm[mat];
    float s = 0.f, q = 0.f;
    int r0 = chunk * 128;
#pragma unroll 4
    for (int r = r0; r < r0 + 128; r++) {
        float x = M[(size_t)r * C + col] * rn[r];   // bitwise == old normalized copy
        s += x;
        q += x * x;
    }
    g_colsum[mat][chunk][col] = s;
    g_colsq[mat][chunk][col]  = q;
}

// ---------------- kernel 3: fp16 warp-MMA GEMM + count epilogue + fused recheck -
// R12 mainloop (best measured). Tail: per-CTA exact fp32 recheck of its own
// smem band-pair list, distributed warp-per-pair (overlaps other CTAs' GEMM).
#define TM 128
#define TN 128
#define TK 64
#define JT 4                              // column tiles per CTA
#define STAGES 3
#define NTHR 256
#define STAGE_A (TM * 128)
#define STAGE_B (TN * 128)
#define STAGE_BYTES (STAGE_A + STAGE_B)   // 32768
#define WLIST_OFF (STAGES * STAGE_BYTES)  // 98304
#define SMEM_SIZE (WLIST_OFF + LCAP * 4)  // 106496
#define NCHT (JT * 8)                     // 32 chunks total

__device__ __forceinline__ void ldsm4(uint32_t* r, uint32_t addr) {
    asm volatile("ldmatrix.sync.aligned.m8n8.x4.shared.b16 {%0,%1,%2,%3}, [%4];"
                 : "=r"(r[0]), "=r"(r[1]), "=r"(r[2]), "=r"(r[3]) : "r"(addr));
}
__device__ __forceinline__ void mma16816(float* d, const uint32_t* a, uint32_t b0, uint32_t b1) {
    asm volatile(
        "mma.sync.aligned.m16n8k16.row.col.f32.f16.f16.f32 "
        "{%0,%1,%2,%3}, {%4,%5,%6,%7}, {%8,%9}, {%0,%1,%2,%3};"
        : "+f"(d[0]), "+f"(d[1]), "+f"(d[2]), "+f"(d[3])
        : "r"(a[0]), "r"(a[1]), "r"(a[2]), "r"(a[3]), "r"(b0), "r"(b1));
}

__device__ __forceinline__ void load_tile(uint32_t smem_dst, const __half* __restrict__ src,
                                          int row0, int kk, int tid) {
#pragma unroll
    for (int i = 0; i < 4; i++) {
        int idx = tid + i * NTHR;
        int r  = idx >> 3;
        int cb = (idx & 7) << 4;
        uint32_t dst = smem_dst + r * 128 + (cb ^ ((r & 7) << 4));
        const void* s = (const char*)(src + (size_t)(row0 + r) * C + kk) + cb;
        asm volatile("cp.async.cg.shared.global [%0], [%1], 16;" :: "r"(dst), "l"(s));
    }
}

__global__ void __launch_bounds__(NTHR, 2) gemm_mma_kernel(
        const float* __restrict__ V, const float* __restrict__ T,
        const float* __restrict__ PV, const float* __restrict__ PT) {
    extern __shared__ char smem[];
    uint32_t sb = smem_u32(smem);
    int tid = threadIdx.x, lane = tid & 31, wid = tid >> 5;
    int z = blockIdx.z;
    int row0 = blockIdx.y * TM;
    int col_base = blockIdx.x * (TN * JT);

    const __half* Ah = g_Ah[z];
    const __half* Bh = g_Bh[z];

    __shared__ int s_n;
    uint32_t* s_list = (uint32_t*)(smem + WLIST_OFF);
    if (tid == 0) s_n = 0;

    auto load_chunk = [&](int t, int stage) {
        int kk = (t & 7) * TK;
        int jc = col_base + (t >> 3) * TN;
        uint32_t s = sb + stage * STAGE_BYTES;
        load_tile(s, Ah, row0, kk, tid);
        load_tile(s + STAGE_A, Bh, jc, kk, tid);
    };

    int wm = (wid >> 2) * 64;   // warp M offset
    int wn = (wid & 3) * 32;    // warp N offset

    float acc[4][4][4];
#pragma unroll
    for (int a = 0; a < 4; a++)
#pragma unroll
        for (int j = 0; j < 4; j++)
#pragma unroll
            for (int q = 0; q < 4; q++) acc[a][j][q] = 0.f;

    int cnt_lo[4] = {0, 0, 0, 0};
    int cnt_hi[4] = {0, 0, 0, 0};

    load_chunk(0, 0);
    asm volatile("cp.async.commit_group;");
    load_chunk(1, 1);
    asm volatile("cp.async.commit_group;");

    int arow = wm + (lane & 15);
    int acb  = (lane >> 4) << 4;
    int bg   = lane >> 3;
    int bn   = wn + (bg >> 1) * 8 + (lane & 7);
    int bcb  = (bg & 1) << 4;

    const float* Dg = g_diag[z];
    int* cnt = g_cnt[z];

    int cur = 0, pre = 2;
    for (int t = 0; t < NCHT; t++) {
        asm volatile("cp.async.wait_group %0;" :: "n"(1));
        __syncthreads();
        if (t + 2 < NCHT) load_chunk(t + 2, pre);
        asm volatile("cp.async.commit_group;");

        uint32_t smA = sb + cur * STAGE_BYTES;
        uint32_t smB = smA + STAGE_A;
#pragma unroll
        for (int ks = 0; ks < 4; ks++) {
            uint32_t af[4][4], bf[2][4];
            int kc = ks * 32;
#pragma unroll
            for (int am = 0; am < 4; am++) {
                int row = arow + am * 16;
                ldsm4(af[am], smA + row * 128 + ((kc + acb) ^ ((row & 7) << 4)));
            }
#pragma unroll
            for (int p = 0; p < 2; p++) {
                int n = bn + p * 16;
                ldsm4(bf[p], smB + n * 128 + ((kc + bcb) ^ ((n & 7) << 4)));
            }
#pragma unroll
            for (int p = 0; p < 2; p++)
#pragma unroll
                for (int am = 0; am < 4; am++) {
                    mma16816(acc[am][2 * p],     af[am], bf[p][0], bf[p][1]);
                    mma16816(acc[am][2 * p + 1], af[am], bf[p][2], bf[p][3]);
                }
        }
        if (++cur == STAGES) cur = 0;
        if (++pre == STAGES) pre = 0;

        if ((t & 7) == 7) {
            // -------- branchless per-tile epilogue --------
            int col0 = col_base + (t >> 3) * TN;
            uint32_t bm0 = 0, bm1 = 0;   // 64-bit band mask; bit = am*16 + j*4 + q
#pragma unroll
            for (int am = 0; am < 4; am++) {
                int rlo = row0 + wm + am * 16 + (lane >> 2);
                float dl = __ldg(&Dg[rlo]);
                float dh = __ldg(&Dg[rlo + 8]);
                float dlp = dl + THETA, dlm = dl - THETA;
                float dhp = dh + THETA, dhm = dh - THETA;
                int clo = 0, chi = 0;
#pragma unroll
                for (int j = 0; j < 4; j++) {
                    float v0 = acc[am][j][0], v1 = acc[am][j][1];
                    float v2 = acc[am][j][2], v3 = acc[am][j][3];
                    bool g0 = v0 > dlp, g1 = v1 > dlp;
                    bool g2 = v2 > dhp, g3 = v3 > dhp;
                    clo += (int)g0 + (int)g1;
                    chi += (int)g2 + (int)g3;
                    uint32_t b = (uint32_t)((v0 > dlm) != g0)
                               | ((uint32_t)((v1 > dlm) != g1) << 1)
                               | ((uint32_t)((v2 > dhm) != g2) << 2)
                               | ((uint32_t)((v3 > dhm) != g3) << 3);
                    int sh = am * 16 + j * 4;
                    if (am < 2) bm0 |= b << sh;
                    else        bm1 |= b << (sh - 32);
                    acc[am][j][0] = acc[am][j][1] = acc[am][j][2] = acc[am][j][3] = 0.f;
                }
                cnt_lo[am] += clo;
                cnt_hi[am] += chi;
            }
            if (bm0 | bm1) {
                // rare slow path: decode band bits -> smem worklist
#pragma unroll
                for (int half = 0; half < 2; half++) {
                    uint32_t m = half ? bm1 : bm0;
                    while (m) {
                        int b = __ffs(m) - 1;
                        m &= m - 1;
                        int bit = half * 32 + b;
                        int am = bit >> 4, j = (bit >> 2) & 3, q = bit & 3;
                        int row = row0 + wm + am * 16 + (lane >> 2) + ((q >> 1) << 3);
                        int col = col0 + wn + j * 8 + ((lane & 3) << 1) + (q & 1);
                        int k = atomicAdd(&s_n, 1);
                        if (k < LCAP) s_list[k] = ((uint32_t)row << 13) | (uint32_t)col;
                    }
                }
            }
        }
    }

    // -------- final count reduction: once per kernel --------
#pragma unroll
    for (int am = 0; am < 4; am++) {
        int rlo = row0 + wm + am * 16 + (lane >> 2);
        int clo = cnt_lo[am], chi = cnt_hi[am];
        clo += __shfl_xor_sync(0xffffffffu, clo, 1);
        clo += __shfl_xor_sync(0xffffffffu, clo, 2);
        chi += __shfl_xor_sync(0xffffffffu, chi, 1);
        chi += __shfl_xor_sync(0xffffffffu, chi, 2);
        if ((lane & 3) == 0) {
            atomicAdd(&cnt[rlo], clo);
            atomicAdd(&cnt[rlo + 8], chi);
        }
    }

    // -------- fused recheck: this CTA's band pairs, exact fp32, warp-per-pair ----
    __syncthreads();
    int nb = s_n < LCAP ? s_n : LCAP;
    const float* Araw = z ? T  : V;    // raw A matrix of this problem
    const float* Braw = z ? PV : PT;   // raw B matrix
    const float* rnA  = g_rnorm[z];            // 0:V, 1:T
    const float* rnB  = g_rnorm[3 - z];        // 3:PT (z=0), 2:PV (z=1)
    for (int w = wid; w < nb; w += 8) {
        uint32_t e = s_list[w];
        int i = (int)(e >> 13) & 8191;
        int j = (int)(e & 8191);
        if (i == j) continue;   // diagonal never counts
        const float* a = Araw + (size_t)i * C;
        const float* b = Braw + (size_t)j * C;
        float s = 0.f;
#pragma unroll
        for (int seg = 0; seg < 4; seg++) {
            float4 x = *(const float4*)(a + seg * 128 + lane * 4);
            float4 y = *(const float4*)(b + seg * 128 + lane * 4);
            s += x.x * y.x + x.y * y.y + x.z * y.z + x.w * y.w;
        }
#pragma unroll
        for (int m = 16; m; m >>= 1) s += __shfl_xor_sync(0xffffffffu, s, m);
        if (lane == 0 && s * rnA[i] * rnB[j] > Dg[i]) atomicAdd(&cnt[i], 1);
    }
}

// ---------------- kernel 4: deterministic finalize ------------------------------
__global__ void finalize_kernel(float* __restrict__ out) {
    __shared__ float sm[16];
    int t = threadIdx.x;

    auto bsum = [&](float v) -> float {
#pragma unroll
        for (int m = 16; m; m >>= 1) v += __shfl_xor_sync(0xffffffffu, v, m);
        if ((t & 31) == 0) sm[t >> 5] = v;
        __syncthreads();
        float r = 0.f;
        if (t < 32) {
            r = (t < 16) ? sm[t] : 0.f;
#pragma unroll
            for (int m = 8; m; m >>= 1) r += __shfl_xor_sync(0xffffffffu, r, m);
        }
        __syncthreads();
        return r;
    };

    float s = 0.f;
    for (int i = t; i < N; i += 512) s += g_diag[0][i] + g_diag[1][i];
    float tot = bsum(s);
    if (t == 0) out[0] = -0.5f * tot / (float)N;

    for (int m = 0; m < 4; m++) {
        float S = 0.f, Q = 0.f;
#pragma unroll 8
        for (int ch = 0; ch < 64; ch++) {
            S += g_colsum[m][ch][t];
            Q += g_colsq[m][ch][t];
        }
        float var = (Q - S * S / (float)N) / (float)(N - 1);
        float sd = sqrtf(fmaxf(var, 0.f));
        float tots = bsum(sd);
        if (t == 0) out[1 + m] = tots / (float)C;
    }

    for (int z = 0; z < 2; z++) {
        const int* cnt = g_cnt[z];
        float c1 = 0.f, c5 = 0.f, c10 = 0.f, cm = 0.f;
        for (int i = t; i < N; i += 512) {
            int p = cnt[i];
            c1  += (p < 1)  ? 1.f : 0.f;
            c5  += (p < 5)  ? 1.f : 0.f;
            c10 += (p < 10) ? 1.f : 0.f;
            cm  += (float)p;
        }
        float t1 = bsum(c1);
        float t5 = bsum(c5);
        float t10 = bsum(c10);
        float tm = bsum(cm);
        if (t == 0) {
            out[5 + 4 * z + 0] = t1 / (float)N;
            out[5 + 4 * z + 1] = t5 / (float)N;
            out[5 + 4 * z + 2] = t10 / (float)N;
            out[5 + 4 * z + 3] = tm / (float)N;
        }
    }
}

// ---------------- launch ---------------------------------------------------------
extern "C" void kernel_launch(void* const* d_in, const int* in_sizes, int n_in,
                              void* d_out, int out_size) {
    const float* V  = (const float*)d_in[0];
    const float* T  = (const float*)d_in[1];
    const float* PV = (const float*)d_in[2];
    const float* PT = (const float*)d_in[3];

    cudaFuncSetAttribute(gemm_mma_kernel, cudaFuncAttributeMaxDynamicSharedMemorySize, SMEM_SIZE);

    zero_cnt_kernel<<<16, 512>>>();
    normalize_kernel<<<N, 128>>>(V, T, PV, PT);
    colstats_kernel<<<dim3(64, 4), 512>>>(V, T, PV, PT);
    gemm_mma_kernel<<<dim3(N / (TN * JT), N / TM, 2), NTHR, SMEM_SIZE>>>(V, T, PV, PT);
    finalize_kernel<<<1, 512>>>((float*)d_out);
}